// round 1
// baseline (speedup 1.0000x reference)
#include <cuda_runtime.h>
#include <math.h>

// Problem dims (shape-specialized to this dataset)
#define N 4096
#define G (3 * N)        // 12288 gru gate rows
#define CHUNK 64         // rows per colmv block

// ---------------- device scratch (no allocation allowed) ----------------
__device__ float g_t[N];        // logits buffer (alpha logits / beta logits)
__device__ float g_vec[N];      // softmax output (alpha / beta)
__device__ float g_sk[N];       // GRU hidden state s_k
__device__ float g_u[N];        // u = W2 @ sk
__device__ float g_xk[N];       // x_k
__device__ float g_gi[G];       // w_ih @ xk
__device__ float g_gh[G];       // w_hh @ sk
__device__ float g_logits3[3];  // W3^T @ feat
__device__ float g_Pr[3];       // accumulated probabilities

// ---------------- kernels ----------------

// zero g_t and g_Pr at the start of every launch
__global__ void init_kernel() {
    int i = blockIdx.x * blockDim.x + threadIdx.x;
    if (i < N) g_t[i] = 0.0f;
    if (i < 3) g_Pr[i] = 0.0f;
}

// y[j] += sum_r x[r] * A[r, j]   (A row-major rows x cols, cols == N)
// grid: (N/256, N/CHUNK), block: 256
__global__ void colmv_kernel(const float* __restrict__ A,
                             const float* __restrict__ x,
                             float* __restrict__ y,
                             int step, const int* __restrict__ Kp) {
    if (step >= *Kp) return;
    __shared__ float xs[CHUNK];
    int j = blockIdx.x * blockDim.x + threadIdx.x;
    int r0 = blockIdx.y * CHUNK;
    if (threadIdx.x < CHUNK) xs[threadIdx.x] = x[r0 + threadIdx.x];
    __syncthreads();
    const float* Ap = A + (size_t)r0 * N + j;
    float acc = 0.0f;
#pragma unroll 8
    for (int r = 0; r < CHUNK; r++)
        acc += xs[r] * Ap[(size_t)r * N];
    atomicAdd(&y[j], acc);
}

// y[row] = dot(A[row, :N], x); optionally zero_t[row] = 0 (zero_t has gridDim.x elems)
// grid: rows, block: 128
__global__ void rowmv_kernel(const float* __restrict__ A,
                             const float* __restrict__ x,
                             float* __restrict__ y,
                             float* zero_t,
                             int step, const int* __restrict__ Kp) {
    if (step >= *Kp) return;
    int row = blockIdx.x;
    if (zero_t != nullptr && threadIdx.x == 0) zero_t[row] = 0.0f;
    const float4* A4 = (const float4*)(A + (size_t)row * N);
    const float4* x4 = (const float4*)x;
    float acc = 0.0f;
#pragma unroll 8
    for (int i = threadIdx.x; i < N / 4; i += 128) {
        float4 a = __ldg(&A4[i]);
        float4 b = __ldg(&x4[i]);
        acc += a.x * b.x + a.y * b.y + a.z * b.z + a.w * b.w;
    }
#pragma unroll
    for (int o = 16; o; o >>= 1) acc += __shfl_down_sync(0xffffffffu, acc, o);
    __shared__ float sh[4];
    if ((threadIdx.x & 31) == 0) sh[threadIdx.x >> 5] = acc;
    __syncthreads();
    if (threadIdx.x == 0) y[row] = sh[0] + sh[1] + sh[2] + sh[3];
}

// out = softmax(t) over N elements; also zeroes z1[0:n1], z2[0:n2]
// single block of 1024 threads
__global__ void softmax_kernel(const float* __restrict__ t,
                               float* __restrict__ out,
                               float* z1, int n1, float* z2, int n2,
                               int step, const int* __restrict__ Kp) {
    if (step >= *Kp) return;
    int tid = threadIdx.x;
    __shared__ float red[32];

    // max
    float m = -INFINITY;
    for (int i = tid; i < N; i += 1024) m = fmaxf(m, t[i]);
#pragma unroll
    for (int o = 16; o; o >>= 1) m = fmaxf(m, __shfl_down_sync(0xffffffffu, m, o));
    if ((tid & 31) == 0) red[tid >> 5] = m;
    __syncthreads();
    if (tid < 32) {
        float v = red[tid];
#pragma unroll
        for (int o = 16; o; o >>= 1) v = fmaxf(v, __shfl_down_sync(0xffffffffu, v, o));
        if (tid == 0) red[0] = v;
    }
    __syncthreads();
    float M = red[0];
    __syncthreads();

    // exp and sum
    float s = 0.0f;
    for (int i = tid; i < N; i += 1024) {
        float e = expf(t[i] - M);
        out[i] = e;
        s += e;
    }
#pragma unroll
    for (int o = 16; o; o >>= 1) s += __shfl_down_sync(0xffffffffu, s, o);
    if ((tid & 31) == 0) red[tid >> 5] = s;
    __syncthreads();
    if (tid < 32) {
        float v = red[tid];
#pragma unroll
        for (int o = 16; o; o >>= 1) v += __shfl_down_sync(0xffffffffu, v, o);
        if (tid == 0) red[0] = v;
    }
    __syncthreads();
    float inv = 1.0f / red[0];
    for (int i = tid; i < N; i += 1024) out[i] *= inv;

    // zero extra buffers for the next stage
    if (z1) for (int i = tid; i < n1; i += 1024) z1[i] = 0.0f;
    if (z2) for (int i = tid; i < n2; i += 1024) z2[i] = 0.0f;
}

// GRU cell elementwise + fused W3 feature dot (atomic into g_logits3)
// grid: 16, block: 256  (4096 threads, one per hidden index)
__global__ void gru_featdot_kernel(const float* __restrict__ W3,
                                   int step, const int* __restrict__ Kp) {
    if (step >= *Kp) return;
    int i = blockIdx.x * blockDim.x + threadIdx.x;

    float l0 = 0.0f, l1 = 0.0f, l2 = 0.0f;
    if (i < N) {
        float h = g_sk[i];
        float x = g_xk[i];
        float ir = g_gi[i],         hr = g_gh[i];
        float iz = g_gi[N + i],     hz = g_gh[N + i];
        float in = g_gi[2 * N + i], hn = g_gh[2 * N + i];
        float r = 1.0f / (1.0f + expf(-(ir + hr)));
        float z = 1.0f / (1.0f + expf(-(iz + hz)));
        float nn = tanhf(in + r * hn);
        float hnew = (1.0f - z) * nn + z * h;
        g_sk[i] = hnew;

        float ad = fabsf(hnew - x);
        float pr = hnew * x;
        const float* w0 = W3 + (size_t)i * 3;
        const float* w1 = W3 + (size_t)(N + i) * 3;
        const float* w2 = W3 + (size_t)(2 * N + i) * 3;
        const float* w3 = W3 + (size_t)(3 * N + i) * 3;
        l0 = w0[0] * hnew + w1[0] * x + w2[0] * ad + w3[0] * pr;
        l1 = w0[1] * hnew + w1[1] * x + w2[1] * ad + w3[1] * pr;
        l2 = w0[2] * hnew + w1[2] * x + w2[2] * ad + w3[2] * pr;
    }
#pragma unroll
    for (int o = 16; o; o >>= 1) {
        l0 += __shfl_down_sync(0xffffffffu, l0, o);
        l1 += __shfl_down_sync(0xffffffffu, l1, o);
        l2 += __shfl_down_sync(0xffffffffu, l2, o);
    }
    if ((threadIdx.x & 31) == 0) {
        atomicAdd(&g_logits3[0], l0);
        atomicAdd(&g_logits3[1], l1);
        atomicAdd(&g_logits3[2], l2);
    }
}

// P_r += softmax(logits3) over 3 labels
__global__ void accum3_kernel(int step, const int* __restrict__ Kp) {
    if (step >= *Kp) return;
    if (threadIdx.x == 0 && blockIdx.x == 0) {
        float a = g_logits3[0], b = g_logits3[1], c = g_logits3[2];
        float m = fmaxf(a, fmaxf(b, c));
        float ea = expf(a - m), eb = expf(b - m), ec = expf(c - m);
        float s = ea + eb + ec;
        g_Pr[0] += ea / s;
        g_Pr[1] += eb / s;
        g_Pr[2] += ec / s;
    }
}

__global__ void final_kernel(float* __restrict__ out, const int* __restrict__ Kp) {
    int i = threadIdx.x;
    if (i < 3) out[i] = g_Pr[i] / (float)(*Kp);
}

// ---------------- host launch ----------------
extern "C" void kernel_launch(void* const* d_in, const int* in_sizes, int n_in,
                              void* d_out, int out_size) {
    const float* M_h   = (const float*)d_in[0];
    const float* M_p   = (const float*)d_in[1];
    const float* w1    = (const float*)d_in[2];
    const float* W2    = (const float*)d_in[3];
    const float* W3    = (const float*)d_in[4];
    const float* w_ih  = (const float*)d_in[5];
    const float* w_hh  = (const float*)d_in[6];
    const int*   Kp    = (const int*)d_in[7];
    float* out = (float*)d_out;

    float *t, *vec, *sk, *u, *xk, *gi, *gh, *logits3;
    cudaGetSymbolAddress((void**)&t,       g_t);
    cudaGetSymbolAddress((void**)&vec,     g_vec);
    cudaGetSymbolAddress((void**)&sk,      g_sk);
    cudaGetSymbolAddress((void**)&u,       g_u);
    cudaGetSymbolAddress((void**)&xk,      g_xk);
    cudaGetSymbolAddress((void**)&gi,      g_gi);
    cudaGetSymbolAddress((void**)&gh,      g_gh);
    cudaGetSymbolAddress((void**)&logits3, g_logits3);

    dim3 cgrid(N / 256, N / CHUNK);

    // prologue: alpha = softmax(w1^T M_h); sk0 = alpha @ M_h
    init_kernel<<<(N + 1023) / 1024, 1024>>>();
    colmv_kernel<<<cgrid, 256>>>(M_h, w1, t, 0, Kp);
    softmax_kernel<<<1, 1024>>>(t, vec, sk, N, nullptr, 0, 0, Kp);
    colmv_kernel<<<cgrid, 256>>>(M_h, vec, sk, 0, Kp);

    const int MAX_STEPS = 8;  // dataset K = 8; device-side guard handles K < 8
    for (int s = 0; s < MAX_STEPS; s++) {
        // u = W2 @ sk   (also zeroes g_t for the next colmv)
        rowmv_kernel<<<N, 128>>>(W2, sk, u, t, s, Kp);
        // logits = u^T @ M_p
        colmv_kernel<<<cgrid, 256>>>(M_p, u, t, s, Kp);
        // beta = softmax(logits)   (also zeroes xk and logits3)
        softmax_kernel<<<1, 1024>>>(t, vec, xk, N, logits3, 3, s, Kp);
        // xk = beta^T @ M_p
        colmv_kernel<<<cgrid, 256>>>(M_p, vec, xk, s, Kp);
        // GRU gate matvecs
        rowmv_kernel<<<G, 128>>>(w_ih, xk, gi, nullptr, s, Kp);
        rowmv_kernel<<<G, 128>>>(w_hh, sk, gh, nullptr, s, Kp);
        // GRU elementwise + feature dot into logits3
        gru_featdot_kernel<<<16, 256>>>(W3, s, Kp);
        // P_r += softmax(logits3)
        accum3_kernel<<<1, 32>>>(s, Kp);
    }

    final_kernel<<<1, 32>>>(out, Kp);
}